// round 13
// baseline (speedup 1.0000x reference)
#include <cuda_runtime.h>
#include <cuda_bf16.h>
#include <math.h>
#include <stdint.h>

// Problem constants (fixed by the dataset)
#define BATCH   512
#define IN_DIM  128
#define OUT_DIM 128
#define NFEAT   9                   // silu + 8 basis functions
#define IPB     8                   // input dims per block (k-split)
#define KPAD    96                  // 8 i * 12 padded cols (6 x k16 chunks)
#define NKC     (KPAD / 16)         // 6 k-chunks
#define SPLITS  (IN_DIM / IPB)      // 16 k-splits
#define BM      64                  // batch rows per block
#define MT      (BATCH / BM)        // 8 m-tiles
#define NTHR    512
#define NOUT    (BATCH * OUT_DIM)   // 65536
#define TSTR    104                 // smem row stride in bf16 (208B, conflict-free)
#define SMEM_BYTES ((2 * BM * TSTR + 2 * OUT_DIM * TSTR) * 2)  // 79872

// Scratch (device globals — no allocation in kernel_launch)
__device__ float        g_P[SPLITS * NOUT];  // split-K partials (4.2 MB)
__device__ unsigned int g_cnt[MT];           // per-m-tile completion tickets

// ---------------------------------------------------------------------------
// HMMA m16n8k16 bf16 -> f32 (generic PTX, sm_80+; legal on sm_103 target)
// ---------------------------------------------------------------------------
__device__ __forceinline__ void mma_bf16(float* c, const uint32_t* a,
                                         const uint32_t* b) {
    asm volatile(
        "mma.sync.aligned.m16n8k16.row.col.f32.bf16.bf16.f32 "
        "{%0,%1,%2,%3}, {%4,%5,%6,%7}, {%8,%9}, {%0,%1,%2,%3};\n"
        : "+f"(c[0]), "+f"(c[1]), "+f"(c[2]), "+f"(c[3])
        : "r"(a[0]), "r"(a[1]), "r"(a[2]), "r"(a[3]),
          "r"(b[0]), "r"(b[1]));
}

__device__ __forceinline__ uint32_t pack_hl(float a, float b) {
    // two bf16 in one word: element order = (low, high) little-endian
    __nv_bfloat162 p = __floats2bfloat162_rn(a, b);
    return *(uint32_t*)&p;
}

// ---------------------------------------------------------------------------
// Single kernel, 512 threads, 128 blocks = (8 m-tiles x 16 k-splits):
//   phase 1: build bf16 hi/lo tiles in smem (packed stores, no zero pass),
//            HMMA GEMM (D = Ah*Bh + Ah*Bl + Al*Bh) -> split-K partials
//   last block per m-tile (monotonic ticket) reduces that m-tile -> out
// No global barrier: deadlock-free, no full-chip wait on the slowest block.
// ---------------------------------------------------------------------------
__global__ void __launch_bounds__(NTHR, 1)
fused_kernel(const float* __restrict__ x,
             const float* __restrict__ grid,
             const float* __restrict__ coef,
             const float* __restrict__ sb,
             const float* __restrict__ ss,
             const float* __restrict__ mask,
             float* __restrict__ out) {
    extern __shared__ __nv_bfloat16 sm[];
    __nv_bfloat16* Ah = sm;                          // [BM][TSTR]
    __nv_bfloat16* Al = sm + BM * TSTR;
    __nv_bfloat16* Bh = sm + 2 * BM * TSTR;          // [OUT_DIM][TSTR]
    __nv_bfloat16* Bl = sm + 2 * BM * TSTR + OUT_DIM * TSTR;
    __shared__ unsigned int s_ticket;

    const int t    = threadIdx.x;
    const int warp = t >> 5;
    const int lane = t & 31;
    const int m0   = blockIdx.x * BM;
    const int i0   = blockIdx.y * IPB;

    // ---- uniform extended knot vector (division-free) ----
    const float g0 = grid[0];
    const float g5 = grid[5];
    const float step = (g5 - g0) * 0.2f;
    const float inv1 = __frcp_rn(step);
    const float invr[3] = { inv1, 0.5f * inv1, inv1 * (1.0f / 3.0f) };

    float tk[12];
    tk[0]  = g0 - step * 3.0f;
    tk[1]  = g0 - step * 2.0f;
    tk[2]  = g0 - step;
    tk[3]  = g0;
    tk[4]  = grid[1];
    tk[5]  = grid[2];
    tk[6]  = grid[3];
    tk[7]  = grid[4];
    tk[8]  = g5;
    tk[9]  = g5 + step;
    tk[10] = g5 + step * 2.0f;
    tk[11] = g5 + step * 3.0f;

    // ---- A build: 64 n x 8 i = 512 x-values, 1 per thread ----
    {
        const int n  = t >> 3;
        const int i  = t & 7;
        const float xv = __ldg(&x[(m0 + n) * IN_DIM + i0 + i]);

        const float sig = __frcp_rn(1.0f + __expf(-xv));
        float f[NFEAT];
        f[0] = xv * sig;                      // silu

        float B[11];
#pragma unroll
        for (int m = 0; m < 11; m++)
            B[m] = (xv >= tk[m] && xv < tk[m + 1]) ? 1.0f : 0.0f;
#pragma unroll
        for (int r = 1; r <= 3; r++) {
            const float iv = invr[r - 1];
#pragma unroll
            for (int m = 0; m < 11 - r; m++) {
                float alpha = (xv - tk[m]) * iv;
                float beta  = (tk[m + r + 1] - xv) * iv;
                B[m] = alpha * B[m] + beta * B[m + 1];
            }
        }
#pragma unroll
        for (int j = 0; j < 8; j++) f[1 + j] = B[j];

        float fh[NFEAT], fl[NFEAT];
#pragma unroll
        for (int j = 0; j < NFEAT; j++) {
            const __nv_bfloat16 h = __float2bfloat16(f[j]);
            fh[j] = __bfloat162float(h);
            fl[j] = f[j] - fh[j];
        }

        // packed stores: 6 uint32 per tile (cols i*12 .. i*12+11, pads = 0)
        uint32_t* ph = (uint32_t*)&Ah[n * TSTR + i * 12];
        uint32_t* pl = (uint32_t*)&Al[n * TSTR + i * 12];
        ph[0] = pack_hl(fh[0], fh[1]); pl[0] = pack_hl(fl[0], fl[1]);
        ph[1] = pack_hl(fh[2], fh[3]); pl[1] = pack_hl(fl[2], fl[3]);
        ph[2] = pack_hl(fh[4], fh[5]); pl[2] = pack_hl(fl[4], fl[5]);
        ph[3] = pack_hl(fh[6], fh[7]); pl[3] = pack_hl(fl[6], fl[7]);
        ph[4] = pack_hl(fh[8], 0.f);   pl[4] = pack_hl(fl[8], 0.f);
        ph[5] = 0u;                    pl[5] = 0u;
    }

    // ---- B build: 128 o x 8 i = 1024 (o,i) pairs, 2 per thread ----
#pragma unroll
    for (int q = 0; q < 2; q++) {
        const int p = t + NTHR * q;
        const int o = p >> 3;
        const int i = p & 7;
        const int s = o * IN_DIM + i0 + i;

        const float4 c0 = __ldg((const float4*)&coef[s * 8]);
        const float4 c1 = __ldg((const float4*)&coef[s * 8 + 4]);
        const float mk  = __ldg(&mask[s]);
        const float wsc = mk * __ldg(&ss[s]);

        float w[NFEAT];
        w[0] = mk * __ldg(&sb[s]);
        w[1] = wsc * c0.x; w[2] = wsc * c0.y; w[3] = wsc * c0.z; w[4] = wsc * c0.w;
        w[5] = wsc * c1.x; w[6] = wsc * c1.y; w[7] = wsc * c1.z; w[8] = wsc * c1.w;

        float wh[NFEAT], wl[NFEAT];
#pragma unroll
        for (int j = 0; j < NFEAT; j++) {
            const __nv_bfloat16 h = __float2bfloat16(w[j]);
            wh[j] = __bfloat162float(h);
            wl[j] = w[j] - wh[j];
        }

        uint32_t* ph = (uint32_t*)&Bh[o * TSTR + i * 12];
        uint32_t* pl = (uint32_t*)&Bl[o * TSTR + i * 12];
        ph[0] = pack_hl(wh[0], wh[1]); pl[0] = pack_hl(wl[0], wl[1]);
        ph[1] = pack_hl(wh[2], wh[3]); pl[1] = pack_hl(wl[2], wl[3]);
        ph[2] = pack_hl(wh[4], wh[5]); pl[2] = pack_hl(wl[4], wl[5]);
        ph[3] = pack_hl(wh[6], wh[7]); pl[3] = pack_hl(wl[6], wl[7]);
        ph[4] = pack_hl(wh[8], 0.f);   pl[4] = pack_hl(wl[8], 0.f);
        ph[5] = 0u;                    pl[5] = 0u;
    }

    __syncthreads();

    // ---- HMMA GEMM ----
    // warp = (wm 0..3, wn 0..3): rows wm*16..+16, cols wn*32..+32 (4 n8 tiles)
    // frag coords: qr = lane>>2, qc = (lane&3)*2
    const int wm = warp & 3;
    const int wn = warp >> 2;
    const int qr = lane >> 2;
    const int qc = (lane & 3) * 2;

    float acc[4][4];
#pragma unroll
    for (int a = 0; a < 4; a++)
#pragma unroll
        for (int b = 0; b < 4; b++) acc[a][b] = 0.f;

#pragma unroll
    for (int kc = 0; kc < NKC; kc++) {
        // A fragments for this k-chunk (hi/lo)
        uint32_t ah[4], al[4];
        {
            const int r0 = (wm * 16 + qr) * TSTR + kc * 16 + qc;
            const int r8 = r0 + 8 * TSTR;
            ah[0] = *(const uint32_t*)&Ah[r0];
            ah[1] = *(const uint32_t*)&Ah[r8];
            ah[2] = *(const uint32_t*)&Ah[r0 + 8];
            ah[3] = *(const uint32_t*)&Ah[r8 + 8];
            al[0] = *(const uint32_t*)&Al[r0];
            al[1] = *(const uint32_t*)&Al[r8];
            al[2] = *(const uint32_t*)&Al[r0 + 8];
            al[3] = *(const uint32_t*)&Al[r8 + 8];
        }
#pragma unroll
        for (int nt = 0; nt < 4; nt++) {
            const int b0 = (wn * 32 + nt * 8 + qr) * TSTR + kc * 16 + qc;
            uint32_t bh[2], bl[2];
            bh[0] = *(const uint32_t*)&Bh[b0];
            bh[1] = *(const uint32_t*)&Bh[b0 + 8];
            bl[0] = *(const uint32_t*)&Bl[b0];
            bl[1] = *(const uint32_t*)&Bl[b0 + 8];

            mma_bf16(acc[nt], ah, bh);   // Ah*Bh
            mma_bf16(acc[nt], ah, bl);   // Ah*Bl
            mma_bf16(acc[nt], al, bh);   // Al*Bh
        }
    }

    // ---- store partials ----
    {
        float* P = &g_P[blockIdx.y * NOUT];
#pragma unroll
        for (int nt = 0; nt < 4; nt++) {
            const int row = m0 + wm * 16 + qr;
            const int col = wn * 32 + nt * 8 + qc;
            *(float2*)&P[row * OUT_DIM + col]       = make_float2(acc[nt][0], acc[nt][1]);
            *(float2*)&P[(row + 8) * OUT_DIM + col] = make_float2(acc[nt][2], acc[nt][3]);
        }
    }

    // ---- last-block-per-m-tile reduces (monotonic ticket; replay-safe) ----
    __threadfence();                  // partials visible before ticket
    __syncthreads();
    if (t == 0)
        s_ticket = atomicAdd(&g_cnt[blockIdx.x], 1u) & (SPLITS - 1);
    __syncthreads();
    if (s_ticket != SPLITS - 1)
        return;                       // not last: done
    __threadfence();                  // acquire: order partial reads

    // reduce this m-tile: 64 rows x 128 cols = 8192 outputs, 16 per thread
    const int base = m0 * OUT_DIM;
#pragma unroll
    for (int rep = 0; rep < (BM * OUT_DIM) / NTHR; rep++) {
        const int idx = base + rep * NTHR + t;
        float v[SPLITS];
#pragma unroll
        for (int q = 0; q < SPLITS; q++)
            v[q] = g_P[q * NOUT + idx];
        float s = 0.0f;
#pragma unroll
        for (int q = 0; q < SPLITS; q++)
            s += v[q];
        out[idx] = s;
    }
}

// ---------------------------------------------------------------------------
extern "C" void kernel_launch(void* const* d_in, const int* in_sizes, int n_in,
                              void* d_out, int out_size) {
    const float* x    = (const float*)d_in[0];
    const float* grid = (const float*)d_in[1];
    const float* coef = (const float*)d_in[2];
    const float* sb   = (const float*)d_in[3];
    const float* ss   = (const float*)d_in[4];
    const float* mask = (const float*)d_in[5];
    float* out = (float*)d_out;

    cudaFuncSetAttribute(fused_kernel,
                         cudaFuncAttributeMaxDynamicSharedMemorySize,
                         SMEM_BYTES);
    fused_kernel<<<dim3(MT, SPLITS), NTHR, SMEM_BYTES>>>(
        x, grid, coef, sb, ss, mask, out);
}

// round 14
// speedup vs baseline: 1.5153x; 1.5153x over previous
#include <cuda_runtime.h>
#include <cuda_bf16.h>
#include <math.h>
#include <stdint.h>

// Problem constants (fixed by the dataset)
#define BATCH   512
#define IN_DIM  128
#define OUT_DIM 128
#define NFEAT   9                   // silu + 8 basis functions
#define IPB     8                   // input dims per block (k-split)
#define KPAD    96                  // 8 i * 12 padded cols (6 x k16 chunks)
#define NKC     (KPAD / 16)         // 6 k-chunks
#define SPLITS  (IN_DIM / IPB)      // 16 k-splits
#define BM      64                  // batch rows per block
#define MT      (BATCH / BM)        // 8 m-tiles
#define NBLK    (MT * SPLITS)       // 128 blocks (single wave on 148 SMs)
#define NTHR    512
#define NOUT    (BATCH * OUT_DIM)   // 65536
#define TSTR    104                 // smem row stride in bf16 (208B, conflict-free)
#define SMEM_BYTES ((2 * BM * TSTR + 2 * OUT_DIM * TSTR) * 2)  // 79872

// Scratch (device globals — no allocation in kernel_launch)
__device__ float        g_P[SPLITS * NOUT];  // split-K partials (4.2 MB)
__device__ unsigned int g_bar;               // monotonic barrier ticket counter

// ---------------------------------------------------------------------------
// HMMA m16n8k16 bf16 -> f32 (generic PTX, sm_80+; legal on sm_103 target)
// ---------------------------------------------------------------------------
__device__ __forceinline__ void mma_bf16(float* c, const uint32_t* a,
                                         const uint32_t* b) {
    asm volatile(
        "mma.sync.aligned.m16n8k16.row.col.f32.bf16.bf16.f32 "
        "{%0,%1,%2,%3}, {%4,%5,%6,%7}, {%8,%9}, {%0,%1,%2,%3};\n"
        : "+f"(c[0]), "+f"(c[1]), "+f"(c[2]), "+f"(c[3])
        : "r"(a[0]), "r"(a[1]), "r"(a[2]), "r"(a[3]),
          "r"(b[0]), "r"(b[1]));
}

__device__ __forceinline__ uint32_t pack_hl(float a, float b) {
    __nv_bfloat162 p = __floats2bfloat162_rn(a, b);
    return *(uint32_t*)&p;
}

// ---------------------------------------------------------------------------
// Single kernel, 512 threads, 128 blocks = (8 m-tiles x 16 k-splits):
//   phase 1: build bf16 hi/lo tiles in smem (packed stores, no zero pass),
//            HMMA GEMM (D = Ah*Bh + Ah*Bl + Al*Bh) -> split-K partials
//   global ticket barrier (proven R12 structure; replay-safe)
//   phase 2: ALL 128 blocks reduce L2-warm partials, 1 output/thread
// ---------------------------------------------------------------------------
__global__ void __launch_bounds__(NTHR, 1)
fused_kernel(const float* __restrict__ x,
             const float* __restrict__ grid,
             const float* __restrict__ coef,
             const float* __restrict__ sb,
             const float* __restrict__ ss,
             const float* __restrict__ mask,
             float* __restrict__ out) {
    extern __shared__ __nv_bfloat16 sm[];
    __nv_bfloat16* Ah = sm;                          // [BM][TSTR]
    __nv_bfloat16* Al = sm + BM * TSTR;
    __nv_bfloat16* Bh = sm + 2 * BM * TSTR;          // [OUT_DIM][TSTR]
    __nv_bfloat16* Bl = sm + 2 * BM * TSTR + OUT_DIM * TSTR;
    __shared__ unsigned int s_target;

    const int t    = threadIdx.x;
    const int warp = t >> 5;
    const int lane = t & 31;
    const int m0   = blockIdx.x * BM;
    const int i0   = blockIdx.y * IPB;

    // ---- uniform extended knot vector (division-free) ----
    const float g0 = grid[0];
    const float g5 = grid[5];
    const float step = (g5 - g0) * 0.2f;
    const float inv1 = __frcp_rn(step);
    const float invr[3] = { inv1, 0.5f * inv1, inv1 * (1.0f / 3.0f) };

    float tk[12];
    tk[0]  = g0 - step * 3.0f;
    tk[1]  = g0 - step * 2.0f;
    tk[2]  = g0 - step;
    tk[3]  = g0;
    tk[4]  = grid[1];
    tk[5]  = grid[2];
    tk[6]  = grid[3];
    tk[7]  = grid[4];
    tk[8]  = g5;
    tk[9]  = g5 + step;
    tk[10] = g5 + step * 2.0f;
    tk[11] = g5 + step * 3.0f;

    // ---- A build: 64 n x 8 i = 512 x-values, 1 per thread ----
    {
        const int n  = t >> 3;
        const int i  = t & 7;
        const float xv = __ldg(&x[(m0 + n) * IN_DIM + i0 + i]);

        const float sig = __frcp_rn(1.0f + __expf(-xv));
        float f[NFEAT];
        f[0] = xv * sig;                      // silu

        float B[11];
#pragma unroll
        for (int m = 0; m < 11; m++)
            B[m] = (xv >= tk[m] && xv < tk[m + 1]) ? 1.0f : 0.0f;
#pragma unroll
        for (int r = 1; r <= 3; r++) {
            const float iv = invr[r - 1];
#pragma unroll
            for (int m = 0; m < 11 - r; m++) {
                float alpha = (xv - tk[m]) * iv;
                float beta  = (tk[m + r + 1] - xv) * iv;
                B[m] = alpha * B[m] + beta * B[m + 1];
            }
        }
#pragma unroll
        for (int j = 0; j < 8; j++) f[1 + j] = B[j];

        float fh[NFEAT], fl[NFEAT];
#pragma unroll
        for (int j = 0; j < NFEAT; j++) {
            const __nv_bfloat16 h = __float2bfloat16(f[j]);
            fh[j] = __bfloat162float(h);
            fl[j] = f[j] - fh[j];
        }

        // packed stores: cols i*12 .. i*12+11 (pads zeroed explicitly)
        uint32_t* ph = (uint32_t*)&Ah[n * TSTR + i * 12];
        uint32_t* pl = (uint32_t*)&Al[n * TSTR + i * 12];
        ph[0] = pack_hl(fh[0], fh[1]); pl[0] = pack_hl(fl[0], fl[1]);
        ph[1] = pack_hl(fh[2], fh[3]); pl[1] = pack_hl(fl[2], fl[3]);
        ph[2] = pack_hl(fh[4], fh[5]); pl[2] = pack_hl(fl[4], fl[5]);
        ph[3] = pack_hl(fh[6], fh[7]); pl[3] = pack_hl(fl[6], fl[7]);
        ph[4] = pack_hl(fh[8], 0.f);   pl[4] = pack_hl(fl[8], 0.f);
        ph[5] = 0u;                    pl[5] = 0u;
    }

    // ---- B build: 128 o x 8 i = 1024 (o,i) pairs, 2 per thread ----
#pragma unroll
    for (int q = 0; q < 2; q++) {
        const int p = t + NTHR * q;
        const int o = p >> 3;
        const int i = p & 7;
        const int s = o * IN_DIM + i0 + i;

        const float4 c0 = __ldg((const float4*)&coef[s * 8]);
        const float4 c1 = __ldg((const float4*)&coef[s * 8 + 4]);
        const float mk  = __ldg(&mask[s]);
        const float wsc = mk * __ldg(&ss[s]);

        float w[NFEAT];
        w[0] = mk * __ldg(&sb[s]);
        w[1] = wsc * c0.x; w[2] = wsc * c0.y; w[3] = wsc * c0.z; w[4] = wsc * c0.w;
        w[5] = wsc * c1.x; w[6] = wsc * c1.y; w[7] = wsc * c1.z; w[8] = wsc * c1.w;

        float wh[NFEAT], wl[NFEAT];
#pragma unroll
        for (int j = 0; j < NFEAT; j++) {
            const __nv_bfloat16 h = __float2bfloat16(w[j]);
            wh[j] = __bfloat162float(h);
            wl[j] = w[j] - wh[j];
        }

        uint32_t* ph = (uint32_t*)&Bh[o * TSTR + i * 12];
        uint32_t* pl = (uint32_t*)&Bl[o * TSTR + i * 12];
        ph[0] = pack_hl(wh[0], wh[1]); pl[0] = pack_hl(wl[0], wl[1]);
        ph[1] = pack_hl(wh[2], wh[3]); pl[1] = pack_hl(wl[2], wl[3]);
        ph[2] = pack_hl(wh[4], wh[5]); pl[2] = pack_hl(wl[4], wl[5]);
        ph[3] = pack_hl(wh[6], wh[7]); pl[3] = pack_hl(wl[6], wl[7]);
        ph[4] = pack_hl(wh[8], 0.f);   pl[4] = pack_hl(wl[8], 0.f);
        ph[5] = 0u;                    pl[5] = 0u;
    }

    __syncthreads();

    // ---- HMMA GEMM ----
    // warp = (wm 0..3, wn 0..3): rows wm*16..+16, cols wn*32..+32 (4 n8 tiles)
    const int wm = warp & 3;
    const int wn = warp >> 2;
    const int qr = lane >> 2;
    const int qc = (lane & 3) * 2;

    float acc[4][4];
#pragma unroll
    for (int a = 0; a < 4; a++)
#pragma unroll
        for (int b = 0; b < 4; b++) acc[a][b] = 0.f;

#pragma unroll
    for (int kc = 0; kc < NKC; kc++) {
        uint32_t ah[4], al[4];
        {
            const int r0 = (wm * 16 + qr) * TSTR + kc * 16 + qc;
            const int r8 = r0 + 8 * TSTR;
            ah[0] = *(const uint32_t*)&Ah[r0];
            ah[1] = *(const uint32_t*)&Ah[r8];
            ah[2] = *(const uint32_t*)&Ah[r0 + 8];
            ah[3] = *(const uint32_t*)&Ah[r8 + 8];
            al[0] = *(const uint32_t*)&Al[r0];
            al[1] = *(const uint32_t*)&Al[r8];
            al[2] = *(const uint32_t*)&Al[r0 + 8];
            al[3] = *(const uint32_t*)&Al[r8 + 8];
        }
#pragma unroll
        for (int nt = 0; nt < 4; nt++) {
            const int b0 = (wn * 32 + nt * 8 + qr) * TSTR + kc * 16 + qc;
            uint32_t bh[2], bl[2];
            bh[0] = *(const uint32_t*)&Bh[b0];
            bh[1] = *(const uint32_t*)&Bh[b0 + 8];
            bl[0] = *(const uint32_t*)&Bl[b0];
            bl[1] = *(const uint32_t*)&Bl[b0 + 8];

            mma_bf16(acc[nt], ah, bh);   // Ah*Bh
            mma_bf16(acc[nt], ah, bl);   // Ah*Bl
            mma_bf16(acc[nt], al, bh);   // Al*Bh
        }
    }

    // ---- store partials ----
    {
        float* P = &g_P[blockIdx.y * NOUT];
#pragma unroll
        for (int nt = 0; nt < 4; nt++) {
            const int row = m0 + wm * 16 + qr;
            const int col = wn * 32 + nt * 8 + qc;
            *(float2*)&P[row * OUT_DIM + col]       = make_float2(acc[nt][0], acc[nt][1]);
            *(float2*)&P[(row + 8) * OUT_DIM + col] = make_float2(acc[nt][2], acc[nt][3]);
        }
    }

    // ---- grid barrier (monotonic ticket; works across graph replays) ----
    __threadfence();
    __syncthreads();
    if (t == 0) {
        unsigned int ticket = atomicAdd(&g_bar, 1u);
        s_target = ticket - (ticket & (NBLK - 1)) + NBLK;  // epoch base + 128
    }
    __syncthreads();
    if (t == 0) {
        const unsigned int target = s_target;
        while (*(volatile unsigned int*)&g_bar < target) { }
    }
    __syncthreads();
    __threadfence();

    // ---- phase 2: reduce L2-warm partials, 1 output per thread ----
    {
        const int flat = blockIdx.y * MT + blockIdx.x;   // 0..127
        const int idx  = flat * NTHR + t;                // 0..65535
        float v[SPLITS];
#pragma unroll
        for (int q = 0; q < SPLITS; q++)
            v[q] = g_P[q * NOUT + idx];
        float s = 0.0f;
#pragma unroll
        for (int q = 0; q < SPLITS; q++)
            s += v[q];
        out[idx] = s;
    }
}

// ---------------------------------------------------------------------------
extern "C" void kernel_launch(void* const* d_in, const int* in_sizes, int n_in,
                              void* d_out, int out_size) {
    const float* x    = (const float*)d_in[0];
    const float* grid = (const float*)d_in[1];
    const float* coef = (const float*)d_in[2];
    const float* sb   = (const float*)d_in[3];
    const float* ss   = (const float*)d_in[4];
    const float* mask = (const float*)d_in[5];
    float* out = (float*)d_out;

    cudaFuncSetAttribute(fused_kernel,
                         cudaFuncAttributeMaxDynamicSharedMemorySize,
                         SMEM_BYTES);
    fused_kernel<<<dim3(MT, SPLITS), NTHR, SMEM_BYTES>>>(
        x, grid, coef, sb, ss, mask, out);
}